// round 1
// baseline (speedup 1.0000x reference)
#include <cuda_runtime.h>

#define Bb 8
#define Nn 16384
#define Kk 256
#define Dd 20

#define TP 16            // pixels per tile
#define PPB 128          // pixels per block
#define NTILES (PPB/TP)  // 8
#define CH (Nn/PPB)      // 128 chunks per batch

// Per-(chunk,batch,k) partials. Plain stores -> deterministic reduction later.
__device__ float g_partM[(long)CH * Bb * Kk * Dd]; // ~21 MB
__device__ float g_partS[CH * Bb * Kk];            // ~1 MB
__device__ float g_S[Bb * Kk];

__global__ __launch_bounds__(256, 2)
void em_main(const float* __restrict__ gmean,
             const float* __restrict__ gfeat,
             const float* __restrict__ gvalid,
             const float* __restrict__ gadj)
{
    __shared__ float mean_sm[Dd][Kk];              // 20 KB, layout [d][k]
    __shared__ float msq[Kk];                      // 1 KB
    __shared__ __align__(16) float f_sm[TP][Dd];   // 1.25 KB, [pixel][d]
    __shared__ float p_sm[TP][Kk];                 // 16 KB

    const int b   = blockIdx.y;
    const int ch  = blockIdx.x;
    const int n0  = ch * PPB;
    const int tid = threadIdx.x;
    const int kg  = tid & 31;   // lane: k = kg + 32*j
    const int pg  = tid >> 5;   // warp id: pixels 2pg, 2pg+1 of each tile

    // ---- stage mean[b] into smem transposed [d][k] ----
    const float* mb = gmean + b * (Kk * Dd);
    for (int i = tid; i < Kk * Dd; i += 256) {
        int k = i / Dd, d = i - k * Dd;
        mean_sm[d][k] = mb[i];
    }
    __syncthreads();
    {   // per-k squared norm
        float s = 0.f;
#pragma unroll
        for (int d = 0; d < Dd; d++) { float m = mean_sm[d][tid]; s += m * m; }
        msq[tid] = s;
    }

    // Phase-B accumulators: thread t owns k=t, lives across all tiles.
    float macc[Dd];
#pragma unroll
    for (int d = 0; d < Dd; d++) macc[d] = 0.f;
    float sacc = 0.f;

    for (int t = 0; t < NTILES; t++) {
        const int nbase = n0 + t * TP;
        __syncthreads();  // previous tile's Phase B done with f_sm/p_sm

        // ---- cooperative load of the 16-pixel feature tile ----
        for (int i = tid; i < TP * Dd; i += 256) {
            int p = i / Dd, d = i - p * Dd;
            f_sm[p][d] = gfeat[((long)b * Nn + nbase + p) * Dd + d];
        }
        __syncthreads();

        // ================= Phase A: distances + softmax =================
        // Warp pg: pixels na, na+1; lane: 8 strided clusters k = kg+32j.
        const int na = nbase + 2 * pg;
        const float* vrow = gvalid + ((long)b * Nn + na) * Kk;
        const float* arow = gadj   + ((long)b * Nn + na) * Kk;

        // Prefetch mask/offset (independent of dot loop -> latency hidden)
        float v0[8], v1[8], a0[8], a1[8];
#pragma unroll
        for (int j = 0; j < 8; j++) {
            int k = kg + 32 * j;
            v0[j] = vrow[k];        v1[j] = vrow[Kk + k];
            a0[j] = arow[k];        a1[j] = arow[Kk + k];
        }

        float dot0[8], dot1[8];
#pragma unroll
        for (int j = 0; j < 8; j++) { dot0[j] = 0.f; dot1[j] = 0.f; }
        float fsq0 = 0.f, fsq1 = 0.f;
#pragma unroll
        for (int d = 0; d < Dd; d++) {
            float fa = f_sm[2 * pg][d];     // broadcast
            float fb = f_sm[2 * pg + 1][d]; // broadcast
            fsq0 += fa * fa;  fsq1 += fb * fb;
#pragma unroll
            for (int j = 0; j < 8; j++) {
                float m = mean_sm[d][kg + 32 * j];  // conflict-free
                dot0[j] += fa * m;
                dot1[j] += fb * m;
            }
        }

        // logits = -(dist^2 * valid + adjust)   (2*STD^2 == 1)
        float l0[8], l1[8];
        float mx0 = -1e30f, mx1 = -1e30f;
#pragma unroll
        for (int j = 0; j < 8; j++) {
            float mq = msq[kg + 32 * j];
            float d0 = fsq0 - 2.f * dot0[j] + mq;
            float d1 = fsq1 - 2.f * dot1[j] + mq;
            l0[j] = -(d0 * v0[j] + a0[j]);
            l1[j] = -(d1 * v1[j] + a1[j]);
            mx0 = fmaxf(mx0, l0[j]);
            mx1 = fmaxf(mx1, l1[j]);
        }
#pragma unroll
        for (int o = 16; o > 0; o >>= 1) {
            mx0 = fmaxf(mx0, __shfl_xor_sync(0xffffffffu, mx0, o));
            mx1 = fmaxf(mx1, __shfl_xor_sync(0xffffffffu, mx1, o));
        }
        float e0[8], e1[8], s0 = 0.f, s1 = 0.f;
#pragma unroll
        for (int j = 0; j < 8; j++) {
            e0[j] = __expf(l0[j] - mx0);
            e1[j] = __expf(l1[j] - mx1);
            s0 += e0[j];  s1 += e1[j];
        }
#pragma unroll
        for (int o = 16; o > 0; o >>= 1) {
            s0 += __shfl_xor_sync(0xffffffffu, s0, o);
            s1 += __shfl_xor_sync(0xffffffffu, s1, o);
        }
        float r0 = __fdividef(1.f, s0);
        float r1 = __fdividef(1.f, s1);
#pragma unroll
        for (int j = 0; j < 8; j++) {
            int k = kg + 32 * j;
            p_sm[2 * pg][k]     = e0[j] * r0;   // conflict-free stores
            p_sm[2 * pg + 1][k] = e1[j] * r1;
        }
        __syncthreads();

        // ============ Phase B: accumulate M[k][:] and S[k] ============
        // thread t owns k = t; f via broadcast float4 LDS
#pragma unroll
        for (int p = 0; p < TP; p++) {
            float pv = p_sm[p][tid];
            sacc += pv;
            const float4* f4 = reinterpret_cast<const float4*>(&f_sm[p][0]);
#pragma unroll
            for (int q = 0; q < Dd / 4; q++) {
                float4 fv = f4[q];
                macc[4 * q + 0] += pv * fv.x;
                macc[4 * q + 1] += pv * fv.y;
                macc[4 * q + 2] += pv * fv.z;
                macc[4 * q + 3] += pv * fv.w;
            }
        }
    }

    // ---- write per-(chunk,b,k) partials (plain stores, deterministic) ----
    const long base = ((long)ch * Bb + b) * Kk;
    g_partS[base + tid] = sacc;
    float* pm = &g_partM[(base + tid) * Dd];
#pragma unroll
    for (int d = 0; d < Dd; d++) pm[d] = macc[d];
}

__global__ void reduce_S()
{
    int i = blockIdx.x * blockDim.x + threadIdx.x;  // over B*K = 2048
    if (i >= Bb * Kk) return;
    int b = i / Kk, k = i - b * Kk;
    float s = 0.f;
#pragma unroll 4
    for (int ch = 0; ch < CH; ch++)
        s += g_partS[((long)ch * Bb + b) * Kk + k];
    g_S[i] = fmaxf(s, 1e-12f);
}

__global__ void reduce_M(float* __restrict__ out)
{
    int i = blockIdx.x * blockDim.x + threadIdx.x;  // over B*K*D = 40960
    if (i >= Bb * Kk * Dd) return;
    int bk = i / Dd;            // = b*Kk + k
    int d  = i - bk * Dd;
    int b  = bk / Kk, k = bk - b * Kk;
    float m = 0.f;
#pragma unroll 4
    for (int ch = 0; ch < CH; ch++)
        m += g_partM[(((long)ch * Bb + b) * Kk + k) * Dd + d];
    out[i] = m / g_S[bk];
}

extern "C" void kernel_launch(void* const* d_in, const int* in_sizes, int n_in,
                              void* d_out, int out_size)
{
    const float* gmean  = (const float*)d_in[0];
    const float* gfeat  = (const float*)d_in[1];
    const float* gvalid = (const float*)d_in[2];
    const float* gadj   = (const float*)d_in[3];
    float* out = (float*)d_out;

    dim3 grid(CH, Bb);
    em_main<<<grid, 256>>>(gmean, gfeat, gvalid, gadj);
    reduce_S<<<(Bb * Kk + 255) / 256, 256>>>();
    reduce_M<<<(Bb * Kk * Dd + 255) / 256, 256>>>(out);
}

// round 2
// speedup vs baseline: 1.1961x; 1.1961x over previous
#include <cuda_runtime.h>

#define Bb 8
#define Nn 16384
#define Kk 256
#define Dd 20

#define TP 32            // pixels per tile (4 per warp, 8 warps)
#define PPB 128          // pixels per block
#define NTILES (PPB/TP)  // 4
#define CH (Nn/PPB)      // 128 chunks per batch

// Per-(chunk,batch,k) partials. Plain stores -> deterministic reduction later.
__device__ float g_partM[(long)CH * Bb * Kk * Dd]; // ~21 MB
__device__ float g_partS[CH * Bb * Kk];            // ~1 MB

#define SMEM_FLOATS (Dd*Kk + Kk + TP*Dd + TP*Kk)   // 14208 floats = 56832 B

__global__ __launch_bounds__(256, 2)
void em_main(const float* __restrict__ gmean,
             const float* __restrict__ gfeat,
             const float* __restrict__ gvalid,
             const float* __restrict__ gadj)
{
    extern __shared__ float sm[];
    float* mean_sm = sm;               // [Dd][Kk]  transposed, 20 KB
    float* msq     = sm + Dd * Kk;     // [Kk]
    float* f_sm    = msq + Kk;         // [TP][Dd]
    float* p_sm    = f_sm + TP * Dd;   // [TP][Kk]  32 KB

    const int tid = threadIdx.x;
    const int kg  = tid & 31;          // lane
    const int w   = tid >> 5;          // warp 0..7; owns pixels 4w..4w+3
    const int b   = blockIdx.y;
    const int ch  = blockIdx.x;
    const int n0  = ch * PPB;

    // ---- stage mean[b] transposed [d][k] ----
    const float* mb = gmean + (long)b * Kk * Dd;
    for (int i = tid; i < Kk * Dd; i += 256) {
        int k = i / Dd, d = i - k * Dd;
        mean_sm[d * Kk + k] = mb[i];
    }
    __syncthreads();
    {
        float s = 0.f;
#pragma unroll
        for (int d = 0; d < Dd; d++) { float m = mean_sm[d * Kk + tid]; s += m * m; }
        msq[tid] = s;
    }

    // Phase-B accumulators: thread owns k = tid, live across all tiles
    float macc[Dd];
#pragma unroll
    for (int d = 0; d < Dd; d++) macc[d] = 0.f;
    float sacc = 0.f;

    for (int t = 0; t < NTILES; t++) {
        const int nbase = n0 + t * TP;
        __syncthreads();   // msq visible (t=0) / previous Phase B done

        // ---- cooperative feature-tile load: 640 floats = 160 float4 ----
        if (tid < TP * Dd / 4) {
            ((float4*)f_sm)[tid] =
                ((const float4*)(gfeat + ((long)b * Nn + nbase) * Dd))[tid];
        }
        __syncthreads();

        // ================= Phase A: distances + softmax =================
        const int  p0   = 4 * w;
        const long rowb = ((long)b * Nn + nbase + p0) * Kk;
        const float* vr = gvalid + rowb;
        const float* ar = gadj   + rowb;

        // prefetch valid/adjust for px0 (hidden under dot loop)
        float4 cv0 = *(const float4*)(vr + 4 * kg);
        float4 cv1 = *(const float4*)(vr + 128 + 4 * kg);
        float4 ca0 = *(const float4*)(ar + 4 * kg);
        float4 ca1 = *(const float4*)(ar + 128 + 4 * kg);

        float dot[4][8];
#pragma unroll
        for (int p = 0; p < 4; p++)
#pragma unroll
            for (int j = 0; j < 8; j++) dot[p][j] = 0.f;
        float fsq[4] = {0.f, 0.f, 0.f, 0.f};

#pragma unroll
        for (int dq = 0; dq < 5; dq++) {
            float fr[4][4];
#pragma unroll
            for (int p = 0; p < 4; p++) {
                float4 fv = *(const float4*)&f_sm[(p0 + p) * Dd + 4 * dq];
                fr[p][0] = fv.x; fr[p][1] = fv.y; fr[p][2] = fv.z; fr[p][3] = fv.w;
            }
#pragma unroll
            for (int dd = 0; dd < 4; dd++) {
                const int d = 4 * dq + dd;
                float4 m0 = *(const float4*)&mean_sm[d * Kk + 4 * kg];
                float4 m1 = *(const float4*)&mean_sm[d * Kk + 128 + 4 * kg];
                float ma[8] = {m0.x, m0.y, m0.z, m0.w, m1.x, m1.y, m1.z, m1.w};
#pragma unroll
                for (int p = 0; p < 4; p++) {
                    float f = fr[p][dd];
                    fsq[p] += f * f;
#pragma unroll
                    for (int j = 0; j < 8; j++) dot[p][j] += f * ma[j];
                }
            }
        }

        float4 q0 = *(const float4*)&msq[4 * kg];
        float4 q1 = *(const float4*)&msq[128 + 4 * kg];
        float mqa[8] = {q0.x, q0.y, q0.z, q0.w, q1.x, q1.y, q1.z, q1.w};

#pragma unroll
        for (int p = 0; p < 4; p++) {
            // software pipeline: issue next pixel's valid/adjust loads now
            float4 nv0, nv1, na0, na1;
            if (p < 3) {
                const float* vrn = vr + (long)(p + 1) * Kk;
                const float* arn = ar + (long)(p + 1) * Kk;
                nv0 = *(const float4*)(vrn + 4 * kg);
                nv1 = *(const float4*)(vrn + 128 + 4 * kg);
                na0 = *(const float4*)(arn + 4 * kg);
                na1 = *(const float4*)(arn + 128 + 4 * kg);
            }
            float va[8] = {cv0.x, cv0.y, cv0.z, cv0.w, cv1.x, cv1.y, cv1.z, cv1.w};
            float aa[8] = {ca0.x, ca0.y, ca0.z, ca0.w, ca1.x, ca1.y, ca1.z, ca1.w};
            const float c = fsq[p];

            // g = dist^2*valid + adjust ; posteriors = softmax(-g)  (2*STD^2 == 1)
            float g[8];
            float gmn = 3.4e38f;
#pragma unroll
            for (int j = 0; j < 8; j++) {
                float dist = fmaf(-2.f, dot[p][j], c + mqa[j]);
                g[j] = fmaf(dist, va[j], aa[j]);
                gmn  = fminf(gmn, g[j]);
            }
#pragma unroll
            for (int o = 16; o > 0; o >>= 1)
                gmn = fminf(gmn, __shfl_xor_sync(0xffffffffu, gmn, o));

            float e[8];
            float s = 0.f;
#pragma unroll
            for (int j = 0; j < 8; j++) { e[j] = __expf(gmn - g[j]); s += e[j]; }
#pragma unroll
            for (int o = 16; o > 0; o >>= 1)
                s += __shfl_xor_sync(0xffffffffu, s, o);
            const float r = __fdividef(1.f, s);

            *(float4*)&p_sm[(p0 + p) * Kk + 4 * kg] =
                make_float4(e[0] * r, e[1] * r, e[2] * r, e[3] * r);
            *(float4*)&p_sm[(p0 + p) * Kk + 128 + 4 * kg] =
                make_float4(e[4] * r, e[5] * r, e[6] * r, e[7] * r);

            if (p < 3) { cv0 = nv0; cv1 = nv1; ca0 = na0; ca1 = na1; }
        }
        __syncthreads();

        // ============ Phase B: accumulate M[k][:] and S[k] ============
#pragma unroll 4
        for (int p = 0; p < TP; p++) {
            float pv = p_sm[p * Kk + tid];
            sacc += pv;
            const float4* f4 = (const float4*)&f_sm[p * Dd];
#pragma unroll
            for (int q = 0; q < Dd / 4; q++) {
                float4 fv = f4[q];
                macc[4 * q + 0] += pv * fv.x;
                macc[4 * q + 1] += pv * fv.y;
                macc[4 * q + 2] += pv * fv.z;
                macc[4 * q + 3] += pv * fv.w;
            }
        }
    }

    // ---- coalesced per-(chunk,b,k) partials ----
    const long base = ((long)ch * Bb + b) * Kk + tid;
    g_partS[base] = sacc;
    float* pm = &g_partM[base * Dd];
#pragma unroll
    for (int d = 0; d < Dd; d++) pm[d] = macc[d];
}

// One warp per (b,k): strided partial sums + shuffle butterfly. Deterministic.
__global__ void reduce_final(float* __restrict__ out)
{
    const int bk   = blockIdx.x;        // 0..B*K-1
    const int b    = bk >> 8;
    const int k    = bk & 255;
    const int lane = threadIdx.x;       // 32 threads

    float m[Dd];
#pragma unroll
    for (int d = 0; d < Dd; d++) m[d] = 0.f;
    float s = 0.f;

    for (int c = lane; c < CH; c += 32) {
        const long base = ((long)c * Bb + b) * Kk + k;
        s += g_partS[base];
        const float* pm = &g_partM[base * Dd];
#pragma unroll
        for (int d = 0; d < Dd; d++) m[d] += pm[d];
    }
#pragma unroll
    for (int o = 16; o > 0; o >>= 1) {
        s += __shfl_xor_sync(0xffffffffu, s, o);
#pragma unroll
        for (int d = 0; d < Dd; d++)
            m[d] += __shfl_xor_sync(0xffffffffu, m[d], o);
    }
    if (lane == 0) {
        const float den = fmaxf(s, 1e-12f);
#pragma unroll
        for (int d = 0; d < Dd; d++) out[(long)bk * Dd + d] = m[d] / den;
    }
}

extern "C" void kernel_launch(void* const* d_in, const int* in_sizes, int n_in,
                              void* d_out, int out_size)
{
    const float* gmean  = (const float*)d_in[0];
    const float* gfeat  = (const float*)d_in[1];
    const float* gvalid = (const float*)d_in[2];
    const float* gadj   = (const float*)d_in[3];
    float* out = (float*)d_out;

    cudaFuncSetAttribute(em_main, cudaFuncAttributeMaxDynamicSharedMemorySize,
                         SMEM_FLOATS * (int)sizeof(float));

    dim3 grid(CH, Bb);
    em_main<<<grid, 256, SMEM_FLOATS * sizeof(float)>>>(gmean, gfeat, gvalid, gadj);
    reduce_final<<<Bb * Kk, 32>>>(out);
}